// round 15
// baseline (speedup 1.0000x reference)
#include <cuda_runtime.h>
#include <cuda_bf16.h>
#include <math.h>

#define DD   128
#define CC   64
#define LL   64
#define KSP  256              // packed K: [hi | lo]
#define BT   128              // b rows per CTA
#define NTT  128              // l cols per CTA (2 categories)
#define SLAB 16384            // 128 rows x 128B
#define S0 0
#define S1 (1 * SLAB)
#define S2 (2 * SLAB)
#define S3 (3 * SLAB)
#define S4 (4 * SLAB)
#define S5 (5 * SLAB)
#define S6 (6 * SLAB)
#define SMEM_TOTAL (7 * SLAB)   // 112KB

// ---- device scratch (allocation-free) ----
__device__ __nv_bfloat16 gA[65536ull * KSP];   // 32 MB
__device__ __nv_bfloat16 gB[4096ull  * KSP];   // 2 MB

__device__ __forceinline__ unsigned smem_u32(const void* p) {
    unsigned a;
    asm("{ .reg .u64 t; cvta.to.shared.u64 t, %1; cvt.u32.u64 %0, t; }" : "=r"(a) : "l"(p));
    return a;
}
template<int N> __device__ __forceinline__ void cp_wait() {
    asm volatile("cp.async.wait_group %0;" :: "n"(N) : "memory");
}

// ---------------- prep: normalize + bf16 split-pack [hi|lo] ----------------
template<int ROWS_TOTAL>
__global__ void split_pack_kernel(const float* __restrict__ src, __nv_bfloat16* __restrict__ dst) {
    int row  = blockIdx.x * 8 + (threadIdx.x >> 5);
    if (row >= ROWS_TOTAL) return;
    int lane = threadIdx.x & 31;
    float4 v = *reinterpret_cast<const float4*>(src + (size_t)row * DD + lane * 4);
    float s = v.x * v.x + v.y * v.y + v.z * v.z + v.w * v.w;
#pragma unroll
    for (int o = 16; o > 0; o >>= 1) s += __shfl_xor_sync(0xffffffffu, s, o);
    float inv = 1.0f / fmaxf(sqrtf(s), 1e-8f);

    float f[4] = {v.x * inv, v.y * inv, v.z * inv, v.w * inv};
    unsigned short hi[4], lo[4];
#pragma unroll
    for (int i = 0; i < 4; i++) {
        __nv_bfloat16 h = __float2bfloat16_rn(f[i]);
        __nv_bfloat16 l = __float2bfloat16_rn(f[i] - __bfloat162float(h));
        hi[i] = __bfloat16_as_ushort(h);
        lo[i] = __bfloat16_as_ushort(l);
    }
    uint2 hp = make_uint2((unsigned)hi[0] | ((unsigned)hi[1] << 16),
                          (unsigned)hi[2] | ((unsigned)hi[3] << 16));
    uint2 lp = make_uint2((unsigned)lo[0] | ((unsigned)lo[1] << 16),
                          (unsigned)lo[2] | ((unsigned)lo[3] << 16));
    size_t base = (size_t)row * KSP + lane * 4;
    *reinterpret_cast<uint2*>(dst + base)       = hp;  // hi half
    *reinterpret_cast<uint2*>(dst + base + 128) = lp;  // lo half
}

__global__ void init_counts_kernel(const float* __restrict__ leaf, float* __restrict__ counts) {
    int i = blockIdx.x * blockDim.x + threadIdx.x;
    if (i < CC * LL) counts[i] = leaf[i];
}

#define MMA(d, a, b)                                                              \
    asm volatile(                                                                 \
        "mma.sync.aligned.m16n8k16.row.col.f32.bf16.bf16.f32 "                    \
        "{%0,%1,%2,%3},{%4,%5,%6,%7},{%8,%9},{%0,%1,%2,%3};"                      \
        : "+f"((d)[0]), "+f"((d)[1]), "+f"((d)[2]), "+f"((d)[3])                  \
        : "r"((a)[0]), "r"((a)[1]), "r"((a)[2]), "r"((a)[3]),                     \
          "r"((b)[0]), "r"((b)[1]))

// Compute 3 products (Ah*Bh + Al*Bh + Ah*Bl) for one K-half group.
__device__ __forceinline__ void compute_group(
    unsigned sah, unsigned sal, unsigned sbh, unsigned sbl,
    int wm, int wn, int lane, float acc[2][8][4])
{
#pragma unroll
    for (int ks = 0; ks < 4; ks++) {
        unsigned afh[2][4], afl[2][4];
#pragma unroll
        for (int mt = 0; mt < 2; mt++) {
            int row = wm * 32 + mt * 16 + (lane & 15);
            unsigned off = (unsigned)row * 128u + (unsigned)ks * 32u + ((lane >> 4) * 16u);
            unsigned sw  = off ^ ((unsigned)(row & 7) << 4);
            asm volatile("ldmatrix.sync.aligned.m8n8.x4.shared.b16 {%0,%1,%2,%3},[%4];"
                         : "=r"(afh[mt][0]), "=r"(afh[mt][1]), "=r"(afh[mt][2]), "=r"(afh[mt][3])
                         : "r"(sah + sw));
            asm volatile("ldmatrix.sync.aligned.m8n8.x4.shared.b16 {%0,%1,%2,%3},[%4];"
                         : "=r"(afl[mt][0]), "=r"(afl[mt][1]), "=r"(afl[mt][2]), "=r"(afl[mt][3])
                         : "r"(sal + sw));
        }
#pragma unroll
        for (int half = 0; half < 2; half++) {
            unsigned bfh[4][2], bfl[4][2];
#pragma unroll
            for (int np = 0; np < 2; np++) {
                int row = wn * 64 + half * 32 + np * 16 + ((lane & 16) >> 1) + (lane & 7);
                unsigned off = (unsigned)row * 128u + (unsigned)ks * 32u + ((lane & 8) ? 16u : 0u);
                unsigned sw  = off ^ ((unsigned)(row & 7) << 4);
                asm volatile("ldmatrix.sync.aligned.m8n8.x4.shared.b16 {%0,%1,%2,%3},[%4];"
                             : "=r"(bfh[2*np][0]), "=r"(bfh[2*np][1]),
                               "=r"(bfh[2*np+1][0]), "=r"(bfh[2*np+1][1])
                             : "r"(sbh + sw));
                asm volatile("ldmatrix.sync.aligned.m8n8.x4.shared.b16 {%0,%1,%2,%3},[%4];"
                             : "=r"(bfl[2*np][0]), "=r"(bfl[2*np][1]),
                               "=r"(bfl[2*np+1][0]), "=r"(bfl[2*np+1][1])
                             : "r"(sbl + sw));
            }
#pragma unroll
            for (int mt = 0; mt < 2; mt++)
#pragma unroll
                for (int nt = 0; nt < 4; nt++) {
                    float* d = acc[mt][half * 4 + nt];
                    MMA(d, afh[mt], bfh[nt]);
                    MMA(d, afl[mt], bfh[nt]);
                    MMA(d, afh[mt], bfl[nt]);
                }
        }
    }
}

// ---------------- main fused GEMM + max/argmax (mma.sync) ----------------
// 256 threads, 8 warps (4m x 2n), warp tile 32x64, CTA tile 128x128, 2 CTAs/SM
__global__ __launch_bounds__(256, 2)
void cosmax_mma_kernel(float* __restrict__ cos_out, float* __restrict__ counts) {
    extern __shared__ char smem[];
    const unsigned sb = smem_u32(smem);
    const int tid  = threadIdx.x;
    const int lane = tid & 31;
    const int wid  = tid >> 5;
    const int wm   = wid >> 1;     // 0..3 : warp row (32 b-rows)
    const int wn   = wid & 1;      // 0..1 : category within CTA (64 cols)
    const int b0   = blockIdx.x * BT;
    const int l0   = blockIdx.y * NTT;

    float acc[2][8][4];
#pragma unroll
    for (int mt = 0; mt < 2; mt++)
#pragma unroll
        for (int nt = 0; nt < 8; nt++)
#pragma unroll
            for (int c = 0; c < 4; c++) acc[mt][nt][c] = 0.0f;

#define LOAD_SLAB(dstoff, gptr, r0, koff)                                                 \
    {                                                                                     \
        _Pragma("unroll")                                                                 \
        for (int j = 0; j < 4; j++) {                                                     \
            unsigned idx  = (unsigned)j * 256u + (unsigned)tid;                           \
            unsigned row  = idx >> 3;                                                     \
            unsigned col  = (idx & 7) * 16u;                                              \
            unsigned off_ = row * 128u + col;                                             \
            unsigned sw_  = off_ ^ ((row & 7) << 4);                                      \
            const char* g_ = (const char*)(gptr) +                                        \
                ((size_t)((r0) + row) * KSP + (koff)) * 2 + col;                          \
            asm volatile("cp.async.cg.shared.global [%0],[%1],16;"                        \
                         :: "r"(sb + (dstoff) + sw_), "l"(g_) : "memory");                \
        }                                                                                 \
    }
#define COMMIT() asm volatile("cp.async.commit_group;" ::: "memory")

    // Group 0 slabs: Ahi0(S0) Bhi0(S1) Alo0(S2) Blo0(S3)
    // Group 1 slabs: Ahi1(S4) Bhi1(S5) Alo1(S6) Blo1(S0, streamed later)
    LOAD_SLAB(S0, gA, b0, 0);   LOAD_SLAB(S1, gB, l0, 0);   COMMIT();  // G0
    LOAD_SLAB(S2, gA, b0, 128); LOAD_SLAB(S3, gB, l0, 128); COMMIT();  // G1
    LOAD_SLAB(S4, gA, b0, 64);  LOAD_SLAB(S5, gB, l0, 64);  COMMIT();  // G2
    LOAD_SLAB(S6, gA, b0, 192);                             COMMIT();  // G3

    cp_wait<2>();
    __syncthreads();
    compute_group(sb + S0, sb + S2, sb + S1, sb + S3, wm, wn, lane, acc);

    __syncthreads();                       // everyone done reading S0
    LOAD_SLAB(S0, gB, l0, 192); COMMIT();  // G4 = Blo1
    cp_wait<0>();
    __syncthreads();
    compute_group(sb + S4, sb + S6, sb + S5, sb + S0, wm, wn, lane, acc);

    // ---- epilogue: hist lives in reused smem, zeroed post-mainloop ----
    float* hist = reinterpret_cast<float*>(smem);   // 128 floats
    __syncthreads();
    if (tid < 128) hist[tid] = 0.0f;
    __syncthreads();

    const int qcol = (lane & 3) * 2;
#pragma unroll
    for (int mt = 0; mt < 2; mt++) {
#pragma unroll
        for (int h = 0; h < 2; h++) {
            float m = __int_as_float(0xff800000);
            int arg = 0;
#pragma unroll
            for (int nt = 0; nt < 8; nt++) {
                float v0 = acc[mt][nt][2 * h];
                float v1 = acc[mt][nt][2 * h + 1];
                int c0 = nt * 8 + qcol;
                if (v0 > m) { m = v0; arg = c0; }
                if (v1 > m) { m = v1; arg = c0 + 1; }
            }
#pragma unroll
            for (int off = 1; off <= 2; off <<= 1) {
                float om = __shfl_xor_sync(0xffffffffu, m, off);
                int   oa = __shfl_xor_sync(0xffffffffu, arg, off);
                if (om > m || (om == m && oa < arg)) { m = om; arg = oa; }
            }
            if ((lane & 3) == 0) {
                int row = b0 + wm * 32 + mt * 16 + h * 8 + (lane >> 2);
                cos_out[(size_t)row * CC + blockIdx.y * 2 + wn] = m;
                atomicAdd(&hist[wn * LL + arg], 1.0f);
            }
        }
    }
    __syncthreads();
    if (tid < 128) {
        float v = hist[tid];
        if (v != 0.0f)
            atomicAdd(&counts[(blockIdx.y * 2 + (tid >> 6)) * LL + (tid & 63)], v);
    }
#undef LOAD_SLAB
#undef COMMIT
}

extern "C" void kernel_launch(void* const* d_in, const int* in_sizes, int n_in,
                              void* d_out, int out_size) {
    const float* x    = (const float*)d_in[0];
    const float* e    = (const float*)d_in[1];
    const float* leaf = (const float*)d_in[2];
    const int B = in_sizes[0] / DD;            // 65536

    float* cos_out = (float*)d_out;            // [B, C]
    float* counts  = cos_out + (size_t)B * CC; // [C, L]

    __nv_bfloat16 *pA, *pB;
    cudaGetSymbolAddress((void**)&pA, gA);
    cudaGetSymbolAddress((void**)&pB, gB);

    cudaFuncSetAttribute(cosmax_mma_kernel,
                         cudaFuncAttributeMaxDynamicSharedMemorySize, SMEM_TOTAL);

    split_pack_kernel<65536><<<B / 8, 256>>>(x, pA);
    split_pack_kernel<4096><<<(CC * LL) / 8, 256>>>(e, pB);
    init_counts_kernel<<<(CC * LL + 255) / 256, 256>>>(leaf, counts);

    dim3 grid(B / BT, (CC * LL) / NTT);        // (512, 32)
    cosmax_mma_kernel<<<grid, 256, SMEM_TOTAL>>>(cos_out, counts);
}

// round 16
// speedup vs baseline: 1.0096x; 1.0096x over previous
#include <cuda_runtime.h>
#include <cuda_bf16.h>
#include <math.h>

#define DD   128
#define CC   64
#define LL   64
#define KSP  256              // packed K: [hi | lo]
#define BT   128              // b rows per CTA
#define NTT  128              // l cols per CTA (2 categories)
#define SLAB 16384            // 128 rows x 128B
#define S0 0
#define S1 (1 * SLAB)
#define S2 (2 * SLAB)
#define S3 (3 * SLAB)
#define S4 (4 * SLAB)
#define S5 (5 * SLAB)
#define S6 (6 * SLAB)
#define SMEM_TOTAL (7 * SLAB)   // 112KB

// ---- device scratch (allocation-free) ----
__device__ __nv_bfloat16 gA[65536ull * KSP];   // 32 MB
__device__ __nv_bfloat16 gB[4096ull  * KSP];   // 2 MB

__device__ __forceinline__ unsigned smem_u32(const void* p) {
    unsigned a;
    asm("{ .reg .u64 t; cvta.to.shared.u64 t, %1; cvt.u32.u64 %0, t; }" : "=r"(a) : "l"(p));
    return a;
}
template<int N> __device__ __forceinline__ void cp_wait() {
    asm volatile("cp.async.wait_group %0;" :: "n"(N) : "memory");
}

// ---------------- prep: normalize + bf16 split-pack [hi|lo] ----------------
template<int ROWS_TOTAL>
__global__ void split_pack_kernel(const float* __restrict__ src, __nv_bfloat16* __restrict__ dst) {
    int row  = blockIdx.x * 8 + (threadIdx.x >> 5);
    if (row >= ROWS_TOTAL) return;
    int lane = threadIdx.x & 31;
    float4 v = *reinterpret_cast<const float4*>(src + (size_t)row * DD + lane * 4);
    float s = v.x * v.x + v.y * v.y + v.z * v.z + v.w * v.w;
#pragma unroll
    for (int o = 16; o > 0; o >>= 1) s += __shfl_xor_sync(0xffffffffu, s, o);
    float inv = 1.0f / fmaxf(sqrtf(s), 1e-8f);

    float f[4] = {v.x * inv, v.y * inv, v.z * inv, v.w * inv};
    unsigned short hi[4], lo[4];
#pragma unroll
    for (int i = 0; i < 4; i++) {
        __nv_bfloat16 h = __float2bfloat16_rn(f[i]);
        __nv_bfloat16 l = __float2bfloat16_rn(f[i] - __bfloat162float(h));
        hi[i] = __bfloat16_as_ushort(h);
        lo[i] = __bfloat16_as_ushort(l);
    }
    uint2 hp = make_uint2((unsigned)hi[0] | ((unsigned)hi[1] << 16),
                          (unsigned)hi[2] | ((unsigned)hi[3] << 16));
    uint2 lp = make_uint2((unsigned)lo[0] | ((unsigned)lo[1] << 16),
                          (unsigned)lo[2] | ((unsigned)lo[3] << 16));
    size_t base = (size_t)row * KSP + lane * 4;
    *reinterpret_cast<uint2*>(dst + base)       = hp;  // hi half
    *reinterpret_cast<uint2*>(dst + base + 128) = lp;  // lo half
}

__global__ void init_counts_kernel(const float* __restrict__ leaf, float* __restrict__ counts) {
    int i = blockIdx.x * blockDim.x + threadIdx.x;
    if (i < CC * LL) counts[i] = leaf[i];
}

#define MMA(d, a, b)                                                              \
    asm volatile(                                                                 \
        "mma.sync.aligned.m16n8k16.row.col.f32.bf16.bf16.f32 "                    \
        "{%0,%1,%2,%3},{%4,%5,%6,%7},{%8,%9},{%0,%1,%2,%3};"                      \
        : "+f"((d)[0]), "+f"((d)[1]), "+f"((d)[2]), "+f"((d)[3])                  \
        : "r"((a)[0]), "r"((a)[1]), "r"((a)[2]), "r"((a)[3]),                     \
          "r"((b)[0]), "r"((b)[1]))

#define LDSM_A(dst, addr)                                                         \
    asm volatile("ldmatrix.sync.aligned.m8n8.x4.shared.b16 {%0,%1,%2,%3},[%4];"   \
                 : "=r"((dst)[0]), "=r"((dst)[1]), "=r"((dst)[2]), "=r"((dst)[3]) \
                 : "r"(addr))

// Pass A: (Ah*B + Al*B) for one K-half, sharing the B fragments.
__device__ __forceinline__ void compute_passA(
    unsigned sah, unsigned sal, unsigned sbh,
    int wm, int wn, int lane, float acc[2][8][4])
{
#pragma unroll
    for (int ks = 0; ks < 4; ks++) {
        unsigned afh[2][4], afl[2][4];
#pragma unroll
        for (int mt = 0; mt < 2; mt++) {
            int row = wm * 32 + mt * 16 + (lane & 15);
            unsigned off = (unsigned)row * 128u + (unsigned)ks * 32u + ((lane >> 4) * 16u);
            unsigned sw  = off ^ ((unsigned)(row & 7) << 4);
            LDSM_A(afh[mt], sah + sw);
            LDSM_A(afl[mt], sal + sw);
        }
        unsigned bf[8][2];
#pragma unroll
        for (int np = 0; np < 4; np++) {
            int row = wn * 64 + np * 16 + ((lane & 16) >> 1) + (lane & 7);
            unsigned off = (unsigned)row * 128u + (unsigned)ks * 32u + ((lane & 8) ? 16u : 0u);
            unsigned sw  = off ^ ((unsigned)(row & 7) << 4);
            asm volatile("ldmatrix.sync.aligned.m8n8.x4.shared.b16 {%0,%1,%2,%3},[%4];"
                         : "=r"(bf[2*np][0]), "=r"(bf[2*np][1]),
                           "=r"(bf[2*np+1][0]), "=r"(bf[2*np+1][1])
                         : "r"(sbh + sw));
        }
#pragma unroll
        for (int mt = 0; mt < 2; mt++)
#pragma unroll
            for (int nt = 0; nt < 8; nt++) {
                float* d = acc[mt][nt];
                MMA(d, afh[mt], bf[nt]);
                MMA(d, afl[mt], bf[nt]);
            }
    }
}

// Pass B: Ah*Bl for one K-half.
__device__ __forceinline__ void compute_passB(
    unsigned sah, unsigned sbl,
    int wm, int wn, int lane, float acc[2][8][4])
{
#pragma unroll
    for (int ks = 0; ks < 4; ks++) {
        unsigned afh[2][4];
#pragma unroll
        for (int mt = 0; mt < 2; mt++) {
            int row = wm * 32 + mt * 16 + (lane & 15);
            unsigned off = (unsigned)row * 128u + (unsigned)ks * 32u + ((lane >> 4) * 16u);
            unsigned sw  = off ^ ((unsigned)(row & 7) << 4);
            LDSM_A(afh[mt], sah + sw);
        }
        unsigned bf[8][2];
#pragma unroll
        for (int np = 0; np < 4; np++) {
            int row = wn * 64 + np * 16 + ((lane & 16) >> 1) + (lane & 7);
            unsigned off = (unsigned)row * 128u + (unsigned)ks * 32u + ((lane & 8) ? 16u : 0u);
            unsigned sw  = off ^ ((unsigned)(row & 7) << 4);
            asm volatile("ldmatrix.sync.aligned.m8n8.x4.shared.b16 {%0,%1,%2,%3},[%4];"
                         : "=r"(bf[2*np][0]), "=r"(bf[2*np][1]),
                           "=r"(bf[2*np+1][0]), "=r"(bf[2*np+1][1])
                         : "r"(sbl + sw));
        }
#pragma unroll
        for (int mt = 0; mt < 2; mt++)
#pragma unroll
            for (int nt = 0; nt < 8; nt++)
                MMA(acc[mt][nt], afh[mt], bf[nt]);
    }
}

// ---------------- main fused GEMM + max/argmax (mma.sync) ----------------
// 256 threads, 8 warps (4m x 2n), warp tile 32x64, CTA tile 128x128, 2 CTAs/SM
__global__ __launch_bounds__(256, 2)
void cosmax_mma_kernel(float* __restrict__ cos_out, float* __restrict__ counts) {
    extern __shared__ char smem[];
    __shared__ float hist[128];
    const unsigned sb = smem_u32(smem);
    const int tid  = threadIdx.x;
    const int lane = tid & 31;
    const int wid  = tid >> 5;
    const int wm   = wid >> 1;     // 0..3 : warp row (32 b-rows)
    const int wn   = wid & 1;      // 0..1 : category within CTA (64 cols)
    const int b0   = blockIdx.x * BT;
    const int l0   = blockIdx.y * NTT;
    if (tid < 128) hist[tid] = 0.0f;   // ordered before epilogue by mainloop barriers

    float acc[2][8][4];
#pragma unroll
    for (int mt = 0; mt < 2; mt++)
#pragma unroll
        for (int nt = 0; nt < 8; nt++)
#pragma unroll
            for (int c = 0; c < 4; c++) acc[mt][nt][c] = 0.0f;

#define LOAD_SLAB(dstoff, gptr, r0, koff)                                                 \
    {                                                                                     \
        _Pragma("unroll")                                                                 \
        for (int j = 0; j < 4; j++) {                                                     \
            unsigned idx  = (unsigned)j * 256u + (unsigned)tid;                           \
            unsigned row  = idx >> 3;                                                     \
            unsigned col  = (idx & 7) * 16u;                                              \
            unsigned off_ = row * 128u + col;                                             \
            unsigned sw_  = off_ ^ ((row & 7) << 4);                                      \
            const char* g_ = (const char*)(gptr) +                                        \
                ((size_t)((r0) + row) * KSP + (koff)) * 2 + col;                          \
            asm volatile("cp.async.cg.shared.global [%0],[%1],16;"                        \
                         :: "r"(sb + (dstoff) + sw_), "l"(g_) : "memory");                \
        }                                                                                 \
    }
#define COMMIT() asm volatile("cp.async.commit_group;" ::: "memory")

    // Slabs: S0=Ah0 S1=Bh0 S2=Al0 S3=Bl0 S4=Ah1 S5=Bh1 S6=Al1; Bl1 streams into S0.
    LOAD_SLAB(S0, gA, b0, 0);
    LOAD_SLAB(S1, gB, l0, 0);
    LOAD_SLAB(S2, gA, b0, 128);  COMMIT();   // C0: Ah0,Bh0,Al0
    LOAD_SLAB(S3, gB, l0, 128);  COMMIT();   // C1: Bl0
    LOAD_SLAB(S4, gA, b0, 64);
    LOAD_SLAB(S5, gB, l0, 64);   COMMIT();   // C2: Ah1,Bh1
    LOAD_SLAB(S6, gA, b0, 192);  COMMIT();   // C3: Al1

    cp_wait<3>();   // C0 done
    __syncthreads();
    compute_passA(sb + S0, sb + S2, sb + S1, wm, wn, lane, acc);   // Ah0,Al0 x Bh0

    cp_wait<2>();   // C1 done (Bl0)
    __syncthreads();
    compute_passB(sb + S0, sb + S3, wm, wn, lane, acc);            // Ah0 x Bl0

    __syncthreads();                        // all warps done reading S0
    LOAD_SLAB(S0, gB, l0, 192); COMMIT();   // C4: Bl1 -> S0 (hidden behind pass1A)

    cp_wait<1>();   // C2,C3 done
    __syncthreads();
    compute_passA(sb + S4, sb + S6, sb + S5, wm, wn, lane, acc);   // Ah1,Al1 x Bh1

    cp_wait<0>();   // C4 done (Bl1)
    __syncthreads();
    compute_passB(sb + S4, sb + S0, wm, wn, lane, acc);            // Ah1 x Bl1

    // ---- epilogue: in-register max/argmax over this warp's 64-col category ----
    const int qcol = (lane & 3) * 2;
#pragma unroll
    for (int mt = 0; mt < 2; mt++) {
#pragma unroll
        for (int h = 0; h < 2; h++) {
            float m = __int_as_float(0xff800000);
            int arg = 0;
#pragma unroll
            for (int nt = 0; nt < 8; nt++) {
                float v0 = acc[mt][nt][2 * h];
                float v1 = acc[mt][nt][2 * h + 1];
                int c0 = nt * 8 + qcol;
                if (v0 > m) { m = v0; arg = c0; }
                if (v1 > m) { m = v1; arg = c0 + 1; }
            }
#pragma unroll
            for (int off = 1; off <= 2; off <<= 1) {
                float om = __shfl_xor_sync(0xffffffffu, m, off);
                int   oa = __shfl_xor_sync(0xffffffffu, arg, off);
                if (om > m || (om == m && oa < arg)) { m = om; arg = oa; }
            }
            if ((lane & 3) == 0) {
                int row = b0 + wm * 32 + mt * 16 + h * 8 + (lane >> 2);
                cos_out[(size_t)row * CC + blockIdx.y * 2 + wn] = m;
                atomicAdd(&hist[wn * LL + arg], 1.0f);
            }
        }
    }
    __syncthreads();
    if (tid < 128) {
        float v = hist[tid];
        if (v != 0.0f)
            atomicAdd(&counts[(blockIdx.y * 2 + (tid >> 6)) * LL + (tid & 63)], v);
    }
#undef LOAD_SLAB
#undef COMMIT
}

extern "C" void kernel_launch(void* const* d_in, const int* in_sizes, int n_in,
                              void* d_out, int out_size) {
    const float* x    = (const float*)d_in[0];
    const float* e    = (const float*)d_in[1];
    const float* leaf = (const float*)d_in[2];
    const int B = in_sizes[0] / DD;            // 65536

    float* cos_out = (float*)d_out;            // [B, C]
    float* counts  = cos_out + (size_t)B * CC; // [C, L]

    __nv_bfloat16 *pA, *pB;
    cudaGetSymbolAddress((void**)&pA, gA);
    cudaGetSymbolAddress((void**)&pB, gB);

    cudaFuncSetAttribute(cosmax_mma_kernel,
                         cudaFuncAttributeMaxDynamicSharedMemorySize, SMEM_TOTAL);

    split_pack_kernel<65536><<<B / 8, 256>>>(x, pA);
    split_pack_kernel<4096><<<(CC * LL) / 8, 256>>>(e, pB);
    init_counts_kernel<<<(CC * LL + 255) / 256, 256>>>(leaf, counts);

    dim3 grid(B / BT, (CC * LL) / NTT);        // (512, 32)
    cosmax_mma_kernel<<<grid, 256, SMEM_TOTAL>>>(cos_out, counts);
}